// round 1
// baseline (speedup 1.0000x reference)
#include <cuda_runtime.h>
#include <math.h>

#define NN    4096
#define FIN   512
#define FH    128
#define NH    4
#define FOUT  64
#define FCAT  512
#define NEGV  -9.0e15f

// ---------------- scratch (device globals: no allocation allowed) ----------
__device__ float g_hcat[NN * FCAT];   // stage1 per-head features, head h at cols [h*FH, h*FH+FH)
__device__ float g_x2  [NN * FCAT];   // stage1 output (elu(attn@h)) concat -> stage2 input
__device__ float g_h2  [NN * FOUT];   // stage2 features
__device__ float g_s1  [NH * NN];
__device__ float g_s2  [NH * NN];
__device__ float g_m1  [NH * NN];
__device__ float g_inv1[NH * NN];
__device__ float g_s1o [NN];
__device__ float g_s2o [NN];
__device__ float g_m2  [NN];
__device__ float g_inv2[NN];

// ---------------- generic tiled GEMM: C[r, colBase+c] = A@B + bias ---------
// BM=64, BN=64, BK=16, 256 threads, 4x4 microtile. Batched over blockIdx.z.
__global__ __launch_bounds__(256) void gemm_bias_k(
    const float* __restrict__ A, int lda,
    const float* __restrict__ B0, int ldb, int strideB,
    const float* __restrict__ bias0, int strideBias,
    float* __restrict__ C, int ldc, int strideCcol, int K)
{
    const int BM = 64, BN = 64, BK = 16;
    __shared__ float As[BK][BM];
    __shared__ float Bs[BK][BN];

    const float* B    = B0    + (size_t)blockIdx.z * strideB;
    const float* bias = bias0 + (size_t)blockIdx.z * strideBias + blockIdx.x * BN;
    const int colBase = blockIdx.z * strideCcol + blockIdx.x * BN;
    const int rowBase = blockIdx.y * BM;
    const int tid = threadIdx.x;
    const int tx = tid & 15, ty = tid >> 4;

    float acc[4][4] = {};

    for (int k0 = 0; k0 < K; k0 += BK) {
        // A tile 64x16 (transposed into As), one float4 per thread
        {
            int r  = tid >> 2;
            int kc = (tid & 3) << 2;
            float4 a = *(const float4*)(A + (size_t)(rowBase + r) * lda + k0 + kc);
            As[kc + 0][r] = a.x; As[kc + 1][r] = a.y;
            As[kc + 2][r] = a.z; As[kc + 3][r] = a.w;
            // B tile 16x64, one float4 per thread
            int kr = tid >> 4;
            int c  = (tid & 15) << 2;
            *(float4*)&Bs[kr][c] =
                *(const float4*)(B + (size_t)(k0 + kr) * ldb + blockIdx.x * BN + c);
        }
        __syncthreads();
        #pragma unroll
        for (int k = 0; k < BK; k++) {
            float4 ra = *(const float4*)&As[k][ty << 2];
            float4 rb = *(const float4*)&Bs[k][tx << 2];
            float av[4] = {ra.x, ra.y, ra.z, ra.w};
            float bv[4] = {rb.x, rb.y, rb.z, rb.w};
            #pragma unroll
            for (int i = 0; i < 4; i++)
                #pragma unroll
                for (int j = 0; j < 4; j++)
                    acc[i][j] = fmaf(av[i], bv[j], acc[i][j]);
        }
        __syncthreads();
    }
    #pragma unroll
    for (int i = 0; i < 4; i++) {
        int r = rowBase + (ty << 2) + i;
        float4 o;
        o.x = acc[i][0] + bias[(tx << 2) + 0];
        o.y = acc[i][1] + bias[(tx << 2) + 1];
        o.z = acc[i][2] + bias[(tx << 2) + 2];
        o.w = acc[i][3] + bias[(tx << 2) + 3];
        *(float4*)(C + (size_t)r * ldc + colBase + (tx << 2)) = o;
    }
}

// ---------------- per-row attention logits: s1 = h@a1, s2 = h@a2 -----------
// grid (NN, H), blockDim = F (128 or 64)
__global__ void sdot_k(const float* __restrict__ Hmat, int ldh,
                       const float* __restrict__ a1, const float* __restrict__ a2,
                       float* __restrict__ s1, float* __restrict__ s2)
{
    int i = blockIdx.x, h = blockIdx.y;
    int F = blockDim.x, f = threadIdx.x;
    float v  = Hmat[(size_t)i * ldh + h * F + f];
    float p1 = v * a1[h * F + f];
    float p2 = v * a2[h * F + f];
    #pragma unroll
    for (int off = 16; off; off >>= 1) {
        p1 += __shfl_xor_sync(0xffffffffu, p1, off);
        p2 += __shfl_xor_sync(0xffffffffu, p2, off);
    }
    __shared__ float r1[4], r2[4];
    int w = f >> 5;
    if ((f & 31) == 0) { r1[w] = p1; r2[w] = p2; }
    __syncthreads();
    if (f == 0) {
        float a = 0.f, b = 0.f;
        int nw = F >> 5;
        for (int k = 0; k < nw; k++) { a += r1[k]; b += r2[k]; }
        s1[h * gridDim.x + i] = a;
        s2[h * gridDim.x + i] = b;
    }
}

// ---------------- row softmax stats (online max/sum), H heads fused --------
template <int H>
__global__ __launch_bounds__(256) void stats_k(
    const int* __restrict__ adj,
    const float* __restrict__ s1, const float* __restrict__ s2,
    const float* __restrict__ ab,
    float* __restrict__ mOut, float* __restrict__ invOut)
{
    const int i = blockIdx.x;
    const int tid = threadIdx.x;

    float s1v[H], abv[H], m[H], s[H];
    #pragma unroll
    for (int h = 0; h < H; h++) {
        s1v[h] = s1[h * NN + i];
        abv[h] = ab[h];
        m[h] = -INFINITY;
        s[h] = 0.f;
    }
    const int* arow = adj + (size_t)i * NN;
    for (int j = tid; j < NN; j += 256) {
        int a = arow[j];
        #pragma unroll
        for (int h = 0; h < H; h++) {
            float e;
            if (a > 0) {
                float z = s1v[h] + s2[h * NN + j] + abv[h];
                e = z > 0.f ? z : 0.2f * z;
            } else {
                e = NEGV;
            }
            if (e > m[h]) { s[h] = s[h] * __expf(m[h] - e) + 1.f; m[h] = e; }
            else          { s[h] += __expf(e - m[h]); }
        }
    }
    __shared__ float sm[H * 256];
    __shared__ float ss[H * 256];
    #pragma unroll
    for (int h = 0; h < H; h++) { sm[h * 256 + tid] = m[h]; ss[h * 256 + tid] = s[h]; }
    __syncthreads();
    for (int off = 128; off > 0; off >>= 1) {
        if (tid < off) {
            #pragma unroll
            for (int h = 0; h < H; h++) {
                float ma = sm[h * 256 + tid],       sa = ss[h * 256 + tid];
                float mb = sm[h * 256 + tid + off], sb = ss[h * 256 + tid + off];
                float M = fmaxf(ma, mb);
                float S = sa * __expf(ma - M) + sb * __expf(mb - M);
                sm[h * 256 + tid] = M; ss[h * 256 + tid] = S;
            }
        }
        __syncthreads();
    }
    if (tid == 0) {
        #pragma unroll
        for (int h = 0; h < H; h++) {
            mOut[h * NN + i]   = sm[h * 256];
            invOut[h * NN + i] = 1.f / ss[h * 256];
        }
    }
}

// ---------------- stage1 aggregation: elu(P @ h) with on-the-fly P ---------
// grid (NN/64, NH), 256 threads, BM=64, BN=128, BK=32, 4x8 microtile.
__global__ __launch_bounds__(256) void agg1_k(
    const int* __restrict__ adj,
    const float* __restrict__ s1a, const float* __restrict__ s2a,
    const float* __restrict__ ma,  const float* __restrict__ inva,
    const float* __restrict__ ab,
    const float* __restrict__ Hmat, float* __restrict__ outmat)
{
    const int BM = 64, BN = 128, BK = 32;
    __shared__ float Ps[BK][BM + 1];
    __shared__ float Hs[BK][BN];
    __shared__ float s1s[BM], ms[BM], invs[BM];

    const int head = blockIdx.y;
    const int i0 = blockIdx.x * BM;
    const int tid = threadIdx.x;
    if (tid < BM) {
        s1s[tid]  = s1a [head * NN + i0 + tid];
        ms[tid]   = ma  [head * NN + i0 + tid];
        invs[tid] = inva[head * NN + i0 + tid];
    }
    __syncthreads();
    const float abv = ab[head];
    const float* s2h = s2a + head * NN;
    const int tx = tid & 15, ty = tid >> 4;

    float acc[4][8] = {};

    for (int j0 = 0; j0 < NN; j0 += BK) {
        // P tile 64x32 (8 entries/thread): recompute attn probs
        #pragma unroll
        for (int v = 0; v < 8; v++) {
            int idx = tid + v * 256;
            int r = idx >> 5, c = idx & 31;
            int j = j0 + c;
            int a = adj[(size_t)(i0 + r) * NN + j];
            float p = 0.f;
            if (a > 0) {
                float z = s1s[r] + s2h[j] + abv;
                float e = z > 0.f ? z : 0.2f * z;
                p = __expf(e - ms[r]) * invs[r];
            }
            Ps[c][r] = p;
        }
        // H tile 32x128 (4 float4/thread)
        #pragma unroll
        for (int v = 0; v < 4; v++) {
            int idx = tid + v * 256;
            int kr = idx >> 5;
            int c  = (idx & 31) << 2;
            *(float4*)&Hs[kr][c] =
                *(const float4*)(Hmat + (size_t)(j0 + kr) * FCAT + head * FH + c);
        }
        __syncthreads();
        #pragma unroll
        for (int k = 0; k < BK; k++) {
            float rp[4];
            #pragma unroll
            for (int i = 0; i < 4; i++) rp[i] = Ps[k][(ty << 2) + i];
            float4 h0 = *(const float4*)&Hs[k][tx << 2];
            float4 h1 = *(const float4*)&Hs[k][64 + (tx << 2)];
            float rh[8] = {h0.x, h0.y, h0.z, h0.w, h1.x, h1.y, h1.z, h1.w};
            #pragma unroll
            for (int i = 0; i < 4; i++)
                #pragma unroll
                for (int j = 0; j < 8; j++)
                    acc[i][j] = fmaf(rp[i], rh[j], acc[i][j]);
        }
        __syncthreads();
    }
    #pragma unroll
    for (int i = 0; i < 4; i++) {
        int r = i0 + (ty << 2) + i;
        float o[8];
        #pragma unroll
        for (int j = 0; j < 8; j++) {
            float v = acc[i][j];
            o[j] = v > 0.f ? v : expm1f(v);
        }
        float4 q0 = {o[0], o[1], o[2], o[3]};
        float4 q1 = {o[4], o[5], o[6], o[7]};
        *(float4*)(outmat + (size_t)r * FCAT + head * FH + (tx << 2)) = q0;
        *(float4*)(outmat + (size_t)r * FCAT + head * FH + 64 + (tx << 2)) = q1;
    }
}

// ---------------- stage2 aggregation + elu + log_softmax -------------------
// grid NN/64, 256 threads, BM=64, BN=64(=Fout), BK=32, 4x4 microtile.
__global__ __launch_bounds__(256) void agg2_k(
    const int* __restrict__ adj,
    const float* __restrict__ s1a, const float* __restrict__ s2a,
    const float* __restrict__ ma,  const float* __restrict__ inva,
    const float* __restrict__ ab,
    const float* __restrict__ Hmat, float* __restrict__ out)
{
    const int BM = 64, BN = 64, BK = 32;
    __shared__ float Ps[BK][BM + 1];
    __shared__ float Hs[BK][BN];
    __shared__ float Cs[BM][BN + 1];
    __shared__ float s1s[BM], ms[BM], invs[BM];

    const int i0 = blockIdx.x * BM;
    const int tid = threadIdx.x;
    if (tid < BM) {
        s1s[tid]  = s1a [i0 + tid];
        ms[tid]   = ma  [i0 + tid];
        invs[tid] = inva[i0 + tid];
    }
    __syncthreads();
    const float abv = ab[0];
    const int tx = tid & 15, ty = tid >> 4;

    float acc[4][4] = {};

    for (int j0 = 0; j0 < NN; j0 += BK) {
        #pragma unroll
        for (int v = 0; v < 8; v++) {
            int idx = tid + v * 256;
            int r = idx >> 5, c = idx & 31;
            int j = j0 + c;
            int a = adj[(size_t)(i0 + r) * NN + j];
            float p = 0.f;
            if (a > 0) {
                float z = s1s[r] + s2a[j] + abv;
                float e = z > 0.f ? z : 0.2f * z;
                p = __expf(e - ms[r]) * invs[r];
            }
            Ps[c][r] = p;
        }
        #pragma unroll
        for (int v = 0; v < 2; v++) {
            int idx = tid + v * 256;
            int kr = idx >> 4;
            int c  = (idx & 15) << 2;
            *(float4*)&Hs[kr][c] =
                *(const float4*)(Hmat + (size_t)(j0 + kr) * FOUT + c);
        }
        __syncthreads();
        #pragma unroll
        for (int k = 0; k < BK; k++) {
            float rp[4];
            #pragma unroll
            for (int i = 0; i < 4; i++) rp[i] = Ps[k][(ty << 2) + i];
            float4 rb = *(const float4*)&Hs[k][tx << 2];
            float bv[4] = {rb.x, rb.y, rb.z, rb.w};
            #pragma unroll
            for (int i = 0; i < 4; i++)
                #pragma unroll
                for (int j = 0; j < 4; j++)
                    acc[i][j] = fmaf(rp[i], bv[j], acc[i][j]);
        }
        __syncthreads();
    }
    // elu into smem
    #pragma unroll
    for (int i = 0; i < 4; i++) {
        int r = (ty << 2) + i;
        #pragma unroll
        for (int j = 0; j < 4; j++) {
            float v = acc[i][j];
            Cs[r][(tx << 2) + j] = v > 0.f ? v : expm1f(v);
        }
    }
    __syncthreads();
    // row log_softmax (8 warps x 8 rows)
    int warp = tid >> 5, lane = tid & 31;
    #pragma unroll
    for (int rr = 0; rr < 8; rr++) {
        int r = warp * 8 + rr;
        float v0 = Cs[r][lane], v1 = Cs[r][lane + 32];
        float mx = fmaxf(v0, v1);
        #pragma unroll
        for (int off = 16; off; off >>= 1)
            mx = fmaxf(mx, __shfl_xor_sync(0xffffffffu, mx, off));
        float se = expf(v0 - mx) + expf(v1 - mx);
        #pragma unroll
        for (int off = 16; off; off >>= 1)
            se += __shfl_xor_sync(0xffffffffu, se, off);
        float lse = mx + logf(se);
        size_t base = (size_t)(i0 + r) * FOUT;
        out[base + lane]      = v0 - lse;
        out[base + lane + 32] = v1 - lse;
    }
}

// ---------------- launch ----------------------------------------------------
extern "C" void kernel_launch(void* const* d_in, const int* in_sizes, int n_in,
                              void* d_out, int out_size)
{
    const float* X    = (const float*)d_in[0];
    const int*   adj  = (const int*)  d_in[1];
    const float* W_h  = (const float*)d_in[2];
    const float* b_h  = (const float*)d_in[3];
    const float* a1_h = (const float*)d_in[4];
    const float* a2_h = (const float*)d_in[5];
    const float* ab_h = (const float*)d_in[6];
    const float* W_o  = (const float*)d_in[7];
    const float* b_o  = (const float*)d_in[8];
    const float* a1_o = (const float*)d_in[9];
    const float* a2_o = (const float*)d_in[10];
    const float* ab_o = (const float*)d_in[11];
    float* out = (float*)d_out;

    float *hcat, *x2, *h2, *s1, *s2, *m1, *inv1, *s1o, *s2o, *m2, *inv2;
    cudaGetSymbolAddress((void**)&hcat, g_hcat);
    cudaGetSymbolAddress((void**)&x2,   g_x2);
    cudaGetSymbolAddress((void**)&h2,   g_h2);
    cudaGetSymbolAddress((void**)&s1,   g_s1);
    cudaGetSymbolAddress((void**)&s2,   g_s2);
    cudaGetSymbolAddress((void**)&m1,   g_m1);
    cudaGetSymbolAddress((void**)&inv1, g_inv1);
    cudaGetSymbolAddress((void**)&s1o,  g_s1o);
    cudaGetSymbolAddress((void**)&s2o,  g_s2o);
    cudaGetSymbolAddress((void**)&m2,   g_m2);
    cudaGetSymbolAddress((void**)&inv2, g_inv2);

    // 1) per-head features: h = X @ W_h[h] + b_h[h]   -> g_hcat
    {
        dim3 grid(FH / 64, NN / 64, NH);
        gemm_bias_k<<<grid, 256>>>(X, FIN, W_h, FH, FIN * FH, b_h, FH,
                                   hcat, FCAT, FH, FIN);
    }
    // 2) logits s1 = h@a1, s2 = h@a2 per head
    {
        dim3 grid(NN, NH);
        sdot_k<<<grid, FH>>>(hcat, FCAT, a1_h, a2_h, s1, s2);
    }
    // 3) softmax row stats, 4 heads fused over one adjacency pass
    stats_k<NH><<<NN, 256>>>(adj, s1, s2, ab_h, m1, inv1);
    // 4) aggregation + elu -> g_x2 (concat layout)
    {
        dim3 grid(NN / 64, NH);
        agg1_k<<<grid, 256>>>(adj, s1, s2, m1, inv1, ab_h, hcat, x2);
    }
    // 5) stage2 features: h2 = x2 @ W_o + b_o
    {
        dim3 grid(FOUT / 64, NN / 64, 1);
        gemm_bias_k<<<grid, 256>>>(x2, FCAT, W_o, FOUT, 0, b_o, 0,
                                   h2, FOUT, 0, FCAT);
    }
    // 6) stage2 logits
    {
        dim3 grid(NN, 1);
        sdot_k<<<grid, FOUT>>>(h2, FOUT, a1_o, a2_o, s1o, s2o);
    }
    // 7) stage2 stats
    stats_k<1><<<NN, 256>>>(adj, s1o, s2o, ab_o, m2, inv2);
    // 8) stage2 aggregation + elu + log_softmax -> out
    agg2_k<<<NN / 64, 256>>>(adj, s1o, s2o, m2, inv2, ab_o, h2, out);
}

// round 2
// speedup vs baseline: 1.3916x; 1.3916x over previous
#include <cuda_runtime.h>
#include <math.h>

#define NN    4096
#define FIN   512
#define FH    128
#define NH    4
#define FOUT  64
#define FCAT  512
#define NEGV  -9.0e15f
#define KSLICES 8

// ---------------- scratch ----------------------------------------------------
__device__ unsigned g_bits[NN * NN / 32];      // packed adjacency (2 MB)
__device__ float g_hcat[NN * FCAT];
__device__ float g_x2  [NN * FCAT];
__device__ float g_h2  [NN * FOUT];
__device__ float g_s1  [NH * NN];
__device__ float g_t2  [NH * NN];              // s2 + ab
__device__ float g_c1  [NH * NN];              // m + log(sum)
__device__ float g_s1o [NN];
__device__ float g_t2o [NN];
__device__ float g_c2  [NN];
__device__ float g_p2  [KSLICES * NN * FOUT];  // stage2 split-K partials

// ---------------- pack adjacency to bits ------------------------------------
__global__ __launch_bounds__(128) void pack_k(const int* __restrict__ adj,
                                              unsigned* __restrict__ bits)
{
    int i = blockIdx.x;
    int t = threadIdx.x, lane = t & 31, w = t >> 5;
    for (int wd = w; wd < NN / 32; wd += 4) {
        int a = adj[(size_t)i * NN + wd * 32 + lane];
        unsigned m = __ballot_sync(0xffffffffu, a > 0);
        if (lane == 0) bits[i * (NN / 32) + wd] = m;
    }
}

// ---------------- stage1 feature GEMM: hcat = X @ W_h[h] + b_h[h] -----------
// BM=64, BN=128(=FH), BK=16, 128 threads, 8x8 microtile. grid (NN/64, NH)
__global__ __launch_bounds__(128) void gemm1_k(
    const float* __restrict__ A, const float* __restrict__ W,
    const float* __restrict__ bias, float* __restrict__ C)
{
    __shared__ float As[16][68];
    __shared__ float Bs[16][128];
    const int head = blockIdx.y;
    const int rowBase = blockIdx.x * 64;
    const int t = threadIdx.x;
    const int tx = t & 15, ty = t >> 4;
    const float* Wh = W + (size_t)head * FIN * FH;

    float acc[8][8] = {};

    for (int k0 = 0; k0 < FIN; k0 += 16) {
        {   // A tile 64x16 transposed
            int r = t >> 1, kc = (t & 1) << 3;
            float4 a0 = *(const float4*)(A + (size_t)(rowBase + r) * FIN + k0 + kc);
            float4 a1 = *(const float4*)(A + (size_t)(rowBase + r) * FIN + k0 + kc + 4);
            As[kc + 0][r] = a0.x; As[kc + 1][r] = a0.y; As[kc + 2][r] = a0.z; As[kc + 3][r] = a0.w;
            As[kc + 4][r] = a1.x; As[kc + 5][r] = a1.y; As[kc + 6][r] = a1.z; As[kc + 7][r] = a1.w;
        }
        #pragma unroll
        for (int v = 0; v < 4; v++) {   // B tile 16x128
            int idx = t + v * 128;
            int kr = idx >> 5, cc = (idx & 31) << 2;
            *(float4*)&Bs[kr][cc] = *(const float4*)(Wh + (size_t)(k0 + kr) * FH + cc);
        }
        __syncthreads();
        #pragma unroll
        for (int k = 0; k < 16; k++) {
            float4 p0 = *(const float4*)&As[k][ty << 3];
            float4 p1 = *(const float4*)&As[k][(ty << 3) + 4];
            float4 h0 = *(const float4*)&Bs[k][tx << 3];
            float4 h1 = *(const float4*)&Bs[k][(tx << 3) + 4];
            float rp[8] = {p0.x, p0.y, p0.z, p0.w, p1.x, p1.y, p1.z, p1.w};
            float rh[8] = {h0.x, h0.y, h0.z, h0.w, h1.x, h1.y, h1.z, h1.w};
            #pragma unroll
            for (int i = 0; i < 8; i++)
                #pragma unroll
                for (int j = 0; j < 8; j++)
                    acc[i][j] = fmaf(rp[i], rh[j], acc[i][j]);
        }
        __syncthreads();
    }
    #pragma unroll
    for (int i = 0; i < 8; i++) {
        int r = rowBase + (ty << 3) + i;
        float o[8];
        #pragma unroll
        for (int j = 0; j < 8; j++) o[j] = acc[i][j] + bias[head * FH + (tx << 3) + j];
        float4 q0 = {o[0], o[1], o[2], o[3]};
        float4 q1 = {o[4], o[5], o[6], o[7]};
        *(float4*)(C + (size_t)r * FCAT + head * FH + (tx << 3)) = q0;
        *(float4*)(C + (size_t)r * FCAT + head * FH + (tx << 3) + 4) = q1;
    }
}

// ---------------- attention logits: s1 = h@a1, t2 = h@a2 + ab ---------------
__global__ void sdot_k(const float* __restrict__ Hmat, int ldh,
                       const float* __restrict__ a1, const float* __restrict__ a2,
                       const float* __restrict__ ab,
                       float* __restrict__ s1, float* __restrict__ t2)
{
    int i = blockIdx.x, h = blockIdx.y;
    int F = blockDim.x, f = threadIdx.x;
    float v  = Hmat[(size_t)i * ldh + h * F + f];
    float p1 = v * a1[h * F + f];
    float p2 = v * a2[h * F + f];
    #pragma unroll
    for (int off = 16; off; off >>= 1) {
        p1 += __shfl_xor_sync(0xffffffffu, p1, off);
        p2 += __shfl_xor_sync(0xffffffffu, p2, off);
    }
    __shared__ float r1[4], r2[4];
    int w = f >> 5;
    if ((f & 31) == 0) { r1[w] = p1; r2[w] = p2; }
    __syncthreads();
    if (f == 0) {
        float a = 0.f, b = 0.f;
        int nw = F >> 5;
        for (int k = 0; k < nw; k++) { a += r1[k]; b += r2[k]; }
        s1[h * NN + i] = a;
        t2[h * NN + i] = b + ab[h];
    }
}

// ---------------- softmax row stats: c = m + log(sum) -----------------------
template <int H>
__global__ __launch_bounds__(128) void stats_k(
    const unsigned* __restrict__ bits,
    const float* __restrict__ s1, const float* __restrict__ t2,
    float* __restrict__ cOut)
{
    const int i = blockIdx.x, t = threadIdx.x;
    __shared__ unsigned sw[NN / 32];
    __shared__ float red[H * 128];
    sw[t] = bits[i * (NN / 32) + t];
    float s1v[H], m[H];
    #pragma unroll
    for (int h = 0; h < H; h++) { s1v[h] = s1[h * NN + i]; m[h] = NEGV; }
    __syncthreads();
    // pass 1: max
    for (int it = 0; it < 32; it++) {
        unsigned w = sw[it * 4 + (t >> 5)];
        if ((w >> (t & 31)) & 1) {
            int j = it * 128 + t;
            #pragma unroll
            for (int h = 0; h < H; h++) {
                float z = s1v[h] + t2[h * NN + j];
                float l = fmaxf(z, 0.2f * z);
                m[h] = fmaxf(m[h], l);
            }
        }
    }
    #pragma unroll
    for (int h = 0; h < H; h++) red[h * 128 + t] = m[h];
    __syncthreads();
    for (int off = 64; off > 0; off >>= 1) {
        if (t < off)
            #pragma unroll
            for (int h = 0; h < H; h++)
                red[h * 128 + t] = fmaxf(red[h * 128 + t], red[h * 128 + t + off]);
        __syncthreads();
    }
    #pragma unroll
    for (int h = 0; h < H; h++) m[h] = red[h * 128];
    __syncthreads();
    // pass 2: sum of exp
    float s[H];
    #pragma unroll
    for (int h = 0; h < H; h++) s[h] = 0.f;
    for (int it = 0; it < 32; it++) {
        unsigned w = sw[it * 4 + (t >> 5)];
        if ((w >> (t & 31)) & 1) {
            int j = it * 128 + t;
            #pragma unroll
            for (int h = 0; h < H; h++) {
                float z = s1v[h] + t2[h * NN + j];
                float l = fmaxf(z, 0.2f * z);
                s[h] += __expf(l - m[h]);
            }
        }
    }
    #pragma unroll
    for (int h = 0; h < H; h++) red[h * 128 + t] = s[h];
    __syncthreads();
    for (int off = 64; off > 0; off >>= 1) {
        if (t < off)
            #pragma unroll
            for (int h = 0; h < H; h++)
                red[h * 128 + t] += red[h * 128 + t + off];
        __syncthreads();
    }
    if (t == 0)
        #pragma unroll
        for (int h = 0; h < H; h++)
            cOut[h * NN + i] = m[h] + logf(red[h * 128]);
}

// ---------------- stage1 aggregation: elu(P @ h), on-the-fly P --------------
// BM=64, BN=128, BK=16, 128 threads, 8x8. grid (NN/64, NH)
__global__ __launch_bounds__(128) void agg1_k(
    const unsigned* __restrict__ bits,
    const float* __restrict__ s1a, const float* __restrict__ t2a,
    const float* __restrict__ ca,
    const float* __restrict__ Hmat, float* __restrict__ outm)
{
    __shared__ float Ps[16][68];
    __shared__ float Hs[16][128];
    __shared__ float s1s[64], cs[64];
    const int head = blockIdx.y;
    const int i0 = blockIdx.x * 64;
    const int t = threadIdx.x;
    if (t < 64) {
        s1s[t] = s1a[head * NN + i0 + t];
        cs[t]  = ca [head * NN + i0 + t];
    }
    const float* t2h = t2a + head * NN;
    const int tx = t & 15, ty = t >> 4;
    const int pc = t & 15;          // P-gen column
    const int pr0 = (t >> 4) * 8;   // P-gen row base
    __syncthreads();

    float acc[8][8] = {};

    for (int j0 = 0; j0 < NN; j0 += 16) {
        float tv = t2h[j0 + pc];
        int bitpos = (j0 & 31) + pc;
        int wcol = j0 >> 5;
        #pragma unroll
        for (int v = 0; v < 8; v++) {
            int r = pr0 + v;
            unsigned w = bits[(size_t)(i0 + r) * (NN / 32) + wcol];
            float z = s1s[r] + tv;
            float l = fmaxf(z, 0.2f * z);
            float p = ((w >> bitpos) & 1u) ? __expf(l - cs[r]) : 0.f;
            Ps[pc][r] = p;
        }
        #pragma unroll
        for (int v = 0; v < 4; v++) {
            int idx = t + v * 128;
            int kr = idx >> 5, cc = (idx & 31) << 2;
            *(float4*)&Hs[kr][cc] =
                *(const float4*)(Hmat + (size_t)(j0 + kr) * FCAT + head * FH + cc);
        }
        __syncthreads();
        #pragma unroll
        for (int k = 0; k < 16; k++) {
            float4 p0 = *(const float4*)&Ps[k][ty << 3];
            float4 p1 = *(const float4*)&Ps[k][(ty << 3) + 4];
            float4 h0 = *(const float4*)&Hs[k][tx << 3];
            float4 h1 = *(const float4*)&Hs[k][(tx << 3) + 4];
            float rp[8] = {p0.x, p0.y, p0.z, p0.w, p1.x, p1.y, p1.z, p1.w};
            float rh[8] = {h0.x, h0.y, h0.z, h0.w, h1.x, h1.y, h1.z, h1.w};
            #pragma unroll
            for (int i = 0; i < 8; i++)
                #pragma unroll
                for (int j = 0; j < 8; j++)
                    acc[i][j] = fmaf(rp[i], rh[j], acc[i][j]);
        }
        __syncthreads();
    }
    #pragma unroll
    for (int i = 0; i < 8; i++) {
        int r = i0 + (ty << 3) + i;
        float o[8];
        #pragma unroll
        for (int j = 0; j < 8; j++) {
            float v = acc[i][j];
            o[j] = v > 0.f ? v : expm1f(v);
        }
        float4 q0 = {o[0], o[1], o[2], o[3]};
        float4 q1 = {o[4], o[5], o[6], o[7]};
        *(float4*)(outm + (size_t)r * FCAT + head * FH + (tx << 3)) = q0;
        *(float4*)(outm + (size_t)r * FCAT + head * FH + (tx << 3) + 4) = q1;
    }
}

// ---------------- stage2 feature GEMM (small): h2 = x2 @ W_o + b_o ----------
__global__ __launch_bounds__(256) void gemm_bias_k(
    const float* __restrict__ A, int lda,
    const float* __restrict__ B, int ldb,
    const float* __restrict__ bias,
    float* __restrict__ C, int ldc, int K)
{
    const int BM = 64, BN = 64, BK = 16;
    __shared__ float As[BK][BM];
    __shared__ float Bs[BK][BN];
    const int rowBase = blockIdx.y * BM;
    const int tid = threadIdx.x;
    const int tx = tid & 15, ty = tid >> 4;
    float acc[4][4] = {};
    for (int k0 = 0; k0 < K; k0 += BK) {
        {
            int r = tid >> 2, kc = (tid & 3) << 2;
            float4 a = *(const float4*)(A + (size_t)(rowBase + r) * lda + k0 + kc);
            As[kc + 0][r] = a.x; As[kc + 1][r] = a.y;
            As[kc + 2][r] = a.z; As[kc + 3][r] = a.w;
            int kr = tid >> 4, c = (tid & 15) << 2;
            *(float4*)&Bs[kr][c] = *(const float4*)(B + (size_t)(k0 + kr) * ldb + c);
        }
        __syncthreads();
        #pragma unroll
        for (int k = 0; k < BK; k++) {
            float4 ra = *(const float4*)&As[k][ty << 2];
            float4 rb = *(const float4*)&Bs[k][tx << 2];
            float av[4] = {ra.x, ra.y, ra.z, ra.w};
            float bv[4] = {rb.x, rb.y, rb.z, rb.w};
            #pragma unroll
            for (int i = 0; i < 4; i++)
                #pragma unroll
                for (int j = 0; j < 4; j++)
                    acc[i][j] = fmaf(av[i], bv[j], acc[i][j]);
        }
        __syncthreads();
    }
    #pragma unroll
    for (int i = 0; i < 4; i++) {
        int r = rowBase + (ty << 2) + i;
        float4 o;
        o.x = acc[i][0] + bias[(tx << 2) + 0];
        o.y = acc[i][1] + bias[(tx << 2) + 1];
        o.z = acc[i][2] + bias[(tx << 2) + 2];
        o.w = acc[i][3] + bias[(tx << 2) + 3];
        *(float4*)(C + (size_t)r * ldc + (tx << 2)) = o;
    }
}

// ---------------- stage2 aggregation split-K: partials ----------------------
// BM=128, BN=64(=FOUT), BK=16, 128 threads, 8x8. grid (NN/128, KSLICES)
__global__ __launch_bounds__(128) void agg2_k(
    const unsigned* __restrict__ bits,
    const float* __restrict__ s1a, const float* __restrict__ t2a,
    const float* __restrict__ ca,
    const float* __restrict__ Hmat, float* __restrict__ part)
{
    __shared__ float Ps[16][132];
    __shared__ float Hs[16][64];
    __shared__ float s1s[128], cs[128];
    const int i0 = blockIdx.x * 128;
    const int kb = blockIdx.y;
    const int t = threadIdx.x;
    s1s[t] = s1a[i0 + t];
    cs[t]  = ca [i0 + t];
    const int tx = t & 7, ty = t >> 3;
    const int pc = t & 15;
    const int pr0 = (t >> 4) * 16;
    __syncthreads();

    float acc[8][8] = {};
    const int js = kb * (NN / KSLICES);
    const int je = js + (NN / KSLICES);

    for (int j0 = js; j0 < je; j0 += 16) {
        float tv = t2a[j0 + pc];
        int bitpos = (j0 & 31) + pc;
        int wcol = j0 >> 5;
        #pragma unroll
        for (int v = 0; v < 16; v++) {
            int r = pr0 + v;
            unsigned w = bits[(size_t)(i0 + r) * (NN / 32) + wcol];
            float z = s1s[r] + tv;
            float l = fmaxf(z, 0.2f * z);
            float p = ((w >> bitpos) & 1u) ? __expf(l - cs[r]) : 0.f;
            Ps[pc][r] = p;
        }
        #pragma unroll
        for (int v = 0; v < 2; v++) {
            int idx = t + v * 128;
            int kr = idx >> 4, cc = (idx & 15) << 2;
            *(float4*)&Hs[kr][cc] = *(const float4*)(Hmat + (size_t)(j0 + kr) * FOUT + cc);
        }
        __syncthreads();
        #pragma unroll
        for (int k = 0; k < 16; k++) {
            float4 p0 = *(const float4*)&Ps[k][ty << 3];
            float4 p1 = *(const float4*)&Ps[k][(ty << 3) + 4];
            float4 h0 = *(const float4*)&Hs[k][tx << 3];
            float4 h1 = *(const float4*)&Hs[k][(tx << 3) + 4];
            float rp[8] = {p0.x, p0.y, p0.z, p0.w, p1.x, p1.y, p1.z, p1.w};
            float rh[8] = {h0.x, h0.y, h0.z, h0.w, h1.x, h1.y, h1.z, h1.w};
            #pragma unroll
            for (int i = 0; i < 8; i++)
                #pragma unroll
                for (int j = 0; j < 8; j++)
                    acc[i][j] = fmaf(rp[i], rh[j], acc[i][j]);
        }
        __syncthreads();
    }
    #pragma unroll
    for (int i = 0; i < 8; i++) {
        int r = i0 + (ty << 3) + i;
        float4 q0 = {acc[i][0], acc[i][1], acc[i][2], acc[i][3]};
        float4 q1 = {acc[i][4], acc[i][5], acc[i][6], acc[i][7]};
        *(float4*)(part + (size_t)kb * NN * FOUT + (size_t)r * FOUT + (tx << 3)) = q0;
        *(float4*)(part + (size_t)kb * NN * FOUT + (size_t)r * FOUT + (tx << 3) + 4) = q1;
    }
}

// ---------------- combine partials + elu + log_softmax ----------------------
__global__ void combine_k(const float* __restrict__ part, float* __restrict__ out)
{
    int i = blockIdx.x, c = threadIdx.x;  // 64 threads
    float v = 0.f;
    #pragma unroll
    for (int k = 0; k < KSLICES; k++)
        v += part[(size_t)k * NN * FOUT + (size_t)i * FOUT + c];
    float e = v > 0.f ? v : expm1f(v);
    __shared__ float sh[4];
    float m = e;
    #pragma unroll
    for (int off = 16; off; off >>= 1)
        m = fmaxf(m, __shfl_xor_sync(0xffffffffu, m, off));
    if ((c & 31) == 0) sh[c >> 5] = m;
    __syncthreads();
    m = fmaxf(sh[0], sh[1]);
    float s = expf(e - m);
    #pragma unroll
    for (int off = 16; off; off >>= 1)
        s += __shfl_xor_sync(0xffffffffu, s, off);
    if ((c & 31) == 0) sh[2 + (c >> 5)] = s;
    __syncthreads();
    s = sh[2] + sh[3];
    out[(size_t)i * FOUT + c] = e - (m + logf(s));
}

// ---------------- launch -----------------------------------------------------
extern "C" void kernel_launch(void* const* d_in, const int* in_sizes, int n_in,
                              void* d_out, int out_size)
{
    const float* X    = (const float*)d_in[0];
    const int*   adj  = (const int*)  d_in[1];
    const float* W_h  = (const float*)d_in[2];
    const float* b_h  = (const float*)d_in[3];
    const float* a1_h = (const float*)d_in[4];
    const float* a2_h = (const float*)d_in[5];
    const float* ab_h = (const float*)d_in[6];
    const float* W_o  = (const float*)d_in[7];
    const float* b_o  = (const float*)d_in[8];
    const float* a1_o = (const float*)d_in[9];
    const float* a2_o = (const float*)d_in[10];
    const float* ab_o = (const float*)d_in[11];
    float* out = (float*)d_out;

    unsigned* bits; float *hcat, *x2, *h2, *s1, *t2, *c1, *s1o, *t2o, *c2, *p2;
    cudaGetSymbolAddress((void**)&bits, g_bits);
    cudaGetSymbolAddress((void**)&hcat, g_hcat);
    cudaGetSymbolAddress((void**)&x2,   g_x2);
    cudaGetSymbolAddress((void**)&h2,   g_h2);
    cudaGetSymbolAddress((void**)&s1,   g_s1);
    cudaGetSymbolAddress((void**)&t2,   g_t2);
    cudaGetSymbolAddress((void**)&c1,   g_c1);
    cudaGetSymbolAddress((void**)&s1o,  g_s1o);
    cudaGetSymbolAddress((void**)&t2o,  g_t2o);
    cudaGetSymbolAddress((void**)&c2,   g_c2);
    cudaGetSymbolAddress((void**)&p2,   g_p2);

    pack_k<<<NN, 128>>>(adj, bits);

    {   dim3 grid(NN / 64, NH);
        gemm1_k<<<grid, 128>>>(X, W_h, b_h, hcat); }

    {   dim3 grid(NN, NH);
        sdot_k<<<grid, FH>>>(hcat, FCAT, a1_h, a2_h, ab_h, s1, t2); }

    stats_k<NH><<<NN, 128>>>(bits, s1, t2, c1);

    {   dim3 grid(NN / 64, NH);
        agg1_k<<<grid, 128>>>(bits, s1, t2, c1, hcat, x2); }

    {   dim3 grid(1, NN / 64);
        gemm_bias_k<<<grid, 256>>>(x2, FCAT, W_o, FOUT, b_o, h2, FOUT, FCAT); }

    {   dim3 grid(NN, 1);
        sdot_k<<<grid, FOUT>>>(h2, FOUT, a1_o, a2_o, ab_o, s1o, t2o); }

    stats_k<1><<<NN, 128>>>(bits, s1o, t2o, c2);

    {   dim3 grid(NN / 128, KSLICES);
        agg2_k<<<grid, 128>>>(bits, s1o, t2o, c2, h2, p2); }

    combine_k<<<NN, 64>>>(p2, out);
}

// round 3
// speedup vs baseline: 2.2371x; 1.6075x over previous
#include <cuda_runtime.h>
#include <math.h>
#include <stdint.h>

#define NN    4096
#define FIN   512
#define FH    128
#define NH    4
#define FOUT  64
#define FCAT  512
#define KSLICES 8

// ---------------- scratch ----------------------------------------------------
__device__ unsigned g_bits[NN * NN / 32];
__device__ float g_hcat[NN * FCAT];
__device__ float g_x2  [NN * FCAT];
__device__ float g_h2  [NN * FOUT];
__device__ float g_s1  [NH * NN];
__device__ float g_t2  [NH * NN];
__device__ float g_c1  [NH * NN];
__device__ float g_s1o [NN];
__device__ float g_t2o [NN];
__device__ float g_c2  [NN];
__device__ float g_p2  [KSLICES * NN * FOUT];

// ---------------- helpers ----------------------------------------------------
__device__ __forceinline__ uint32_t f2tf32(float x) {
    uint32_t r;
    asm("cvt.rna.tf32.f32 %0, %1;" : "=r"(r) : "f"(x));
    return r;
}
__device__ __forceinline__ void mma8(float* c, const uint32_t* a, const uint32_t* b) {
    asm volatile(
        "mma.sync.aligned.m16n8k8.row.col.f32.tf32.tf32.f32 "
        "{%0,%1,%2,%3},{%4,%5,%6,%7},{%8,%9},{%0,%1,%2,%3};"
        : "+f"(c[0]), "+f"(c[1]), "+f"(c[2]), "+f"(c[3])
        : "r"(a[0]), "r"(a[1]), "r"(a[2]), "r"(a[3]), "r"(b[0]), "r"(b[1]));
}

// ---------------- pack adjacency to bits ------------------------------------
__global__ __launch_bounds__(128) void pack_k(const int* __restrict__ adj,
                                              unsigned* __restrict__ bits)
{
    int i = blockIdx.x;
    int t = threadIdx.x, lane = t & 31, w = t >> 5;
    for (int wd = w; wd < NN / 32; wd += 4) {
        int a = adj[(size_t)i * NN + wd * 32 + lane];
        unsigned m = __ballot_sync(0xffffffffu, a > 0);
        if (lane == 0) bits[i * (NN / 32) + wd] = m;
    }
}

// ---------------- stage1 feature GEMM (tf32 mma): hcat = X@W_h[h]+b_h[h] ----
// BM=64, BN=128, BK=16, 128 threads, warps 2Mx2N (warp tile 32x64).
__global__ __launch_bounds__(128) void gemm1_k(
    const float* __restrict__ A, const float* __restrict__ W,
    const float* __restrict__ bias, float* __restrict__ C)
{
    __shared__ float As[16][72];
    __shared__ float Bs[16][136];
    const int head = blockIdx.y;
    const int rowBase = blockIdx.x * 64;
    const int t = threadIdx.x;
    const int lane = t & 31, wid = t >> 5;
    const int gid = lane >> 2, tig = lane & 3;
    const int mw = wid >> 1, nw = wid & 1;
    const float* Wh = W + (size_t)head * FIN * FH;

    float acc[2][8][4] = {};

    for (int k0 = 0; k0 < FIN; k0 += 16) {
        {   // A tile 64x16 transposed, tf32-rounded
            int r = t >> 1, kc = (t & 1) << 3;
            float4 a0 = *(const float4*)(A + (size_t)(rowBase + r) * FIN + k0 + kc);
            float4 a1 = *(const float4*)(A + (size_t)(rowBase + r) * FIN + k0 + kc + 4);
            As[kc + 0][r] = __uint_as_float(f2tf32(a0.x));
            As[kc + 1][r] = __uint_as_float(f2tf32(a0.y));
            As[kc + 2][r] = __uint_as_float(f2tf32(a0.z));
            As[kc + 3][r] = __uint_as_float(f2tf32(a0.w));
            As[kc + 4][r] = __uint_as_float(f2tf32(a1.x));
            As[kc + 5][r] = __uint_as_float(f2tf32(a1.y));
            As[kc + 6][r] = __uint_as_float(f2tf32(a1.z));
            As[kc + 7][r] = __uint_as_float(f2tf32(a1.w));
        }
        #pragma unroll
        for (int v = 0; v < 4; v++) {   // B tile 16x128
            int idx = t + v * 128;
            int kr = idx >> 5, cc = (idx & 31) << 2;
            float4 b = *(const float4*)(Wh + (size_t)(k0 + kr) * FH + cc);
            float4 o;
            o.x = __uint_as_float(f2tf32(b.x)); o.y = __uint_as_float(f2tf32(b.y));
            o.z = __uint_as_float(f2tf32(b.z)); o.w = __uint_as_float(f2tf32(b.w));
            *(float4*)&Bs[kr][cc] = o;
        }
        __syncthreads();
        #pragma unroll
        for (int kc = 0; kc < 2; kc++) {
            int kk = kc * 8;
            uint32_t af[2][4];
            #pragma unroll
            for (int mt = 0; mt < 2; mt++) {
                int rb = mw * 32 + mt * 16;
                af[mt][0] = __float_as_uint(As[kk + tig][rb + gid]);
                af[mt][1] = __float_as_uint(As[kk + tig][rb + gid + 8]);
                af[mt][2] = __float_as_uint(As[kk + tig + 4][rb + gid]);
                af[mt][3] = __float_as_uint(As[kk + tig + 4][rb + gid + 8]);
            }
            #pragma unroll
            for (int nt = 0; nt < 8; nt++) {
                int cb = nw * 64 + nt * 8;
                uint32_t bf[2];
                bf[0] = __float_as_uint(Bs[kk + tig][cb + gid]);
                bf[1] = __float_as_uint(Bs[kk + tig + 4][cb + gid]);
                mma8(acc[0][nt], af[0], bf);
                mma8(acc[1][nt], af[1], bf);
            }
        }
        __syncthreads();
    }
    #pragma unroll
    for (int mt = 0; mt < 2; mt++) {
        int r0 = rowBase + mw * 32 + mt * 16 + gid;
        #pragma unroll
        for (int nt = 0; nt < 8; nt++) {
            int c0 = nw * 64 + nt * 8 + tig * 2;
            float b0 = bias[head * FH + c0], b1 = bias[head * FH + c0 + 1];
            float2 lo = {acc[mt][nt][0] + b0, acc[mt][nt][1] + b1};
            float2 hi = {acc[mt][nt][2] + b0, acc[mt][nt][3] + b1};
            *(float2*)(C + (size_t)r0 * FCAT + head * FH + c0) = lo;
            *(float2*)(C + (size_t)(r0 + 8) * FCAT + head * FH + c0) = hi;
        }
    }
}

// ---------------- attention logits ------------------------------------------
__global__ void sdot_k(const float* __restrict__ Hmat, int ldh,
                       const float* __restrict__ a1, const float* __restrict__ a2,
                       const float* __restrict__ ab,
                       float* __restrict__ s1, float* __restrict__ t2)
{
    int i = blockIdx.x, h = blockIdx.y;
    int F = blockDim.x, f = threadIdx.x;
    float v  = Hmat[(size_t)i * ldh + h * F + f];
    float p1 = v * a1[h * F + f];
    float p2 = v * a2[h * F + f];
    #pragma unroll
    for (int off = 16; off; off >>= 1) {
        p1 += __shfl_xor_sync(0xffffffffu, p1, off);
        p2 += __shfl_xor_sync(0xffffffffu, p2, off);
    }
    __shared__ float r1[4], r2[4];
    int w = f >> 5;
    if ((f & 31) == 0) { r1[w] = p1; r2[w] = p2; }
    __syncthreads();
    if (f == 0) {
        float a = 0.f, b = 0.f;
        int nw = F >> 5;
        for (int k = 0; k < nw; k++) { a += r1[k]; b += r2[k]; }
        s1[h * NN + i] = a;
        t2[h * NN + i] = b + ab[h];
    }
}

// ---------------- softmax row stats: c = m + log(sum) -----------------------
template <int H>
__global__ __launch_bounds__(128) void stats_k(
    const unsigned* __restrict__ bits,
    const float* __restrict__ s1, const float* __restrict__ t2,
    float* __restrict__ cOut)
{
    const int i = blockIdx.x, t = threadIdx.x;
    __shared__ unsigned sw[NN / 32];
    __shared__ float red[H * 128];
    sw[t] = bits[i * (NN / 32) + t];
    float s1v[H], m[H];
    #pragma unroll
    for (int h = 0; h < H; h++) { s1v[h] = s1[h * NN + i]; m[h] = -9.0e15f; }
    __syncthreads();
    for (int it = 0; it < 32; it++) {
        unsigned w = sw[it * 4 + (t >> 5)];
        if ((w >> (t & 31)) & 1) {
            int j = it * 128 + t;
            #pragma unroll
            for (int h = 0; h < H; h++) {
                float z = s1v[h] + t2[h * NN + j];
                m[h] = fmaxf(m[h], fmaxf(z, 0.2f * z));
            }
        }
    }
    #pragma unroll
    for (int h = 0; h < H; h++) red[h * 128 + t] = m[h];
    __syncthreads();
    for (int off = 64; off > 0; off >>= 1) {
        if (t < off)
            #pragma unroll
            for (int h = 0; h < H; h++)
                red[h * 128 + t] = fmaxf(red[h * 128 + t], red[h * 128 + t + off]);
        __syncthreads();
    }
    #pragma unroll
    for (int h = 0; h < H; h++) m[h] = red[h * 128];
    __syncthreads();
    float s[H];
    #pragma unroll
    for (int h = 0; h < H; h++) s[h] = 0.f;
    for (int it = 0; it < 32; it++) {
        unsigned w = sw[it * 4 + (t >> 5)];
        if ((w >> (t & 31)) & 1) {
            int j = it * 128 + t;
            #pragma unroll
            for (int h = 0; h < H; h++) {
                float z = s1v[h] + t2[h * NN + j];
                float l = fmaxf(z, 0.2f * z);
                s[h] += __expf(l - m[h]);
            }
        }
    }
    #pragma unroll
    for (int h = 0; h < H; h++) red[h * 128 + t] = s[h];
    __syncthreads();
    for (int off = 64; off > 0; off >>= 1) {
        if (t < off)
            #pragma unroll
            for (int h = 0; h < H; h++)
                red[h * 128 + t] += red[h * 128 + t + off];
        __syncthreads();
    }
    if (t == 0)
        #pragma unroll
        for (int h = 0; h < H; h++)
            cOut[h * NN + i] = m[h] + logf(red[h * 128]);
}

// ---------------- stage1 aggregation (tf32 mma): elu(P @ h) -----------------
// BM=64, BN=128, BK=16, 128 threads, warps 2Mx2N (warp tile 32x64).
__global__ __launch_bounds__(128) void agg1_k(
    const unsigned* __restrict__ bits,
    const float* __restrict__ s1a, const float* __restrict__ t2a,
    const float* __restrict__ ca,
    const float* __restrict__ Hmat, float* __restrict__ outm)
{
    __shared__ float Ps[16][72];
    __shared__ float Hs[16][136];
    __shared__ float s1s[64], cs[64];
    const int head = blockIdx.y;
    const int i0 = blockIdx.x * 64;
    const int t = threadIdx.x;
    const int lane = t & 31, wid = t >> 5;
    const int gid = lane >> 2, tig = lane & 3;
    const int mw = wid >> 1, nw = wid & 1;
    if (t < 64) {
        s1s[t] = s1a[head * NN + i0 + t];
        cs[t]  = ca [head * NN + i0 + t];
    }
    const float* t2h = t2a + head * NN;
    // P-gen mapping: conflict-free STS into Ps[k][r] (stride 72: bank = 8k+r mod 32)
    const int pk = (t & 3) + 4 * wid;       // k column 0..15
    const int pr = (t >> 2) & 7;            // row low bits
    __syncthreads();

    float acc[2][8][4] = {};

    for (int j0 = 0; j0 < NN; j0 += 16) {
        const float tv = t2h[j0 + pk];
        const int wcol = j0 >> 5;
        const int bitpos = (j0 & 16) + pk;
        #pragma unroll
        for (int v = 0; v < 8; v++) {
            int r = pr + 8 * v;
            unsigned w = bits[(size_t)(i0 + r) * (NN / 32) + wcol];
            float z = s1s[r] + tv;
            float l = fmaxf(z, 0.2f * z);
            float p = ((w >> bitpos) & 1u) ? __expf(l - cs[r]) : 0.f;
            Ps[pk][r] = __uint_as_float(f2tf32(p));
        }
        #pragma unroll
        for (int v = 0; v < 4; v++) {
            int idx = t + v * 128;
            int kr = idx >> 5, cc = (idx & 31) << 2;
            float4 b = *(const float4*)(Hmat + (size_t)(j0 + kr) * FCAT + head * FH + cc);
            float4 o;
            o.x = __uint_as_float(f2tf32(b.x)); o.y = __uint_as_float(f2tf32(b.y));
            o.z = __uint_as_float(f2tf32(b.z)); o.w = __uint_as_float(f2tf32(b.w));
            *(float4*)&Hs[kr][cc] = o;
        }
        __syncthreads();
        #pragma unroll
        for (int kc = 0; kc < 2; kc++) {
            int kk = kc * 8;
            uint32_t af[2][4];
            #pragma unroll
            for (int mt = 0; mt < 2; mt++) {
                int rb = mw * 32 + mt * 16;
                af[mt][0] = __float_as_uint(Ps[kk + tig][rb + gid]);
                af[mt][1] = __float_as_uint(Ps[kk + tig][rb + gid + 8]);
                af[mt][2] = __float_as_uint(Ps[kk + tig + 4][rb + gid]);
                af[mt][3] = __float_as_uint(Ps[kk + tig + 4][rb + gid + 8]);
            }
            #pragma unroll
            for (int nt = 0; nt < 8; nt++) {
                int cb = nw * 64 + nt * 8;
                uint32_t bf[2];
                bf[0] = __float_as_uint(Hs[kk + tig][cb + gid]);
                bf[1] = __float_as_uint(Hs[kk + tig + 4][cb + gid]);
                mma8(acc[0][nt], af[0], bf);
                mma8(acc[1][nt], af[1], bf);
            }
        }
        __syncthreads();
    }
    #pragma unroll
    for (int mt = 0; mt < 2; mt++) {
        int r0 = i0 + mw * 32 + mt * 16 + gid;
        #pragma unroll
        for (int nt = 0; nt < 8; nt++) {
            int c0 = head * FH + nw * 64 + nt * 8 + tig * 2;
            float v;
            float2 lo, hi;
            v = acc[mt][nt][0]; lo.x = v > 0.f ? v : expm1f(v);
            v = acc[mt][nt][1]; lo.y = v > 0.f ? v : expm1f(v);
            v = acc[mt][nt][2]; hi.x = v > 0.f ? v : expm1f(v);
            v = acc[mt][nt][3]; hi.y = v > 0.f ? v : expm1f(v);
            *(float2*)(outm + (size_t)r0 * FCAT + c0) = lo;
            *(float2*)(outm + (size_t)(r0 + 8) * FCAT + c0) = hi;
        }
    }
}

// ---------------- stage2 feature GEMM (small, SIMT) --------------------------
__global__ __launch_bounds__(256) void gemm_bias_k(
    const float* __restrict__ A, int lda,
    const float* __restrict__ B, int ldb,
    const float* __restrict__ bias,
    float* __restrict__ C, int ldc, int K)
{
    const int BM = 64, BN = 64, BK = 16;
    __shared__ float As[BK][BM];
    __shared__ float Bs[BK][BN];
    const int rowBase = blockIdx.y * BM;
    const int tid = threadIdx.x;
    const int tx = tid & 15, ty = tid >> 4;
    float acc[4][4] = {};
    for (int k0 = 0; k0 < K; k0 += BK) {
        {
            int r = tid >> 2, kc = (tid & 3) << 2;
            float4 a = *(const float4*)(A + (size_t)(rowBase + r) * lda + k0 + kc);
            As[kc + 0][r] = a.x; As[kc + 1][r] = a.y;
            As[kc + 2][r] = a.z; As[kc + 3][r] = a.w;
            int kr = tid >> 4, c = (tid & 15) << 2;
            *(float4*)&Bs[kr][c] = *(const float4*)(B + (size_t)(k0 + kr) * ldb + c);
        }
        __syncthreads();
        #pragma unroll
        for (int k = 0; k < BK; k++) {
            float4 ra = *(const float4*)&As[k][ty << 2];
            float4 rb = *(const float4*)&Bs[k][tx << 2];
            float av[4] = {ra.x, ra.y, ra.z, ra.w};
            float bv[4] = {rb.x, rb.y, rb.z, rb.w};
            #pragma unroll
            for (int i = 0; i < 4; i++)
                #pragma unroll
                for (int j = 0; j < 4; j++)
                    acc[i][j] = fmaf(av[i], bv[j], acc[i][j]);
        }
        __syncthreads();
    }
    #pragma unroll
    for (int i = 0; i < 4; i++) {
        int r = rowBase + (ty << 2) + i;
        float4 o;
        o.x = acc[i][0] + bias[(tx << 2) + 0];
        o.y = acc[i][1] + bias[(tx << 2) + 1];
        o.z = acc[i][2] + bias[(tx << 2) + 2];
        o.w = acc[i][3] + bias[(tx << 2) + 3];
        *(float4*)(C + (size_t)r * ldc + (tx << 2)) = o;
    }
}

// ---------------- stage2 aggregation (tf32 mma, split-K) --------------------
// BM=64, BN=64, BK=16, 128 threads, warps 2Mx2N (warp tile 32x32).
__global__ __launch_bounds__(128) void agg2_k(
    const unsigned* __restrict__ bits,
    const float* __restrict__ s1a, const float* __restrict__ t2a,
    const float* __restrict__ ca,
    const float* __restrict__ Hmat, float* __restrict__ part)
{
    __shared__ float Ps[16][72];
    __shared__ float Hs[16][72];
    __shared__ float s1s[64], cs[64];
    const int i0 = blockIdx.x * 64;
    const int kb = blockIdx.y;
    const int t = threadIdx.x;
    const int lane = t & 31, wid = t >> 5;
    const int gid = lane >> 2, tig = lane & 3;
    const int mw = wid >> 1, nw = wid & 1;
    if (t < 64) { s1s[t] = s1a[i0 + t]; cs[t] = ca[i0 + t]; }
    const int pk = (t & 3) + 4 * wid;
    const int pr = (t >> 2) & 7;
    __syncthreads();

    float acc[2][4][4] = {};
    const int js = kb * (NN / KSLICES);
    const int je = js + (NN / KSLICES);

    for (int j0 = js; j0 < je; j0 += 16) {
        const float tv = t2a[j0 + pk];
        const int wcol = j0 >> 5;
        const int bitpos = (j0 & 16) + pk;
        #pragma unroll
        for (int v = 0; v < 8; v++) {
            int r = pr + 8 * v;
            unsigned w = bits[(size_t)(i0 + r) * (NN / 32) + wcol];
            float z = s1s[r] + tv;
            float l = fmaxf(z, 0.2f * z);
            float p = ((w >> bitpos) & 1u) ? __expf(l - cs[r]) : 0.f;
            Ps[pk][r] = __uint_as_float(f2tf32(p));
        }
        #pragma unroll
        for (int v = 0; v < 2; v++) {
            int idx = t + v * 128;
            int kr = idx >> 4, cc = (idx & 15) << 2;
            float4 b = *(const float4*)(Hmat + (size_t)(j0 + kr) * FOUT + cc);
            float4 o;
            o.x = __uint_as_float(f2tf32(b.x)); o.y = __uint_as_float(f2tf32(b.y));
            o.z = __uint_as_float(f2tf32(b.z)); o.w = __uint_as_float(f2tf32(b.w));
            *(float4*)&Hs[kr][cc] = o;
        }
        __syncthreads();
        #pragma unroll
        for (int kc = 0; kc < 2; kc++) {
            int kk = kc * 8;
            uint32_t af[2][4];
            #pragma unroll
            for (int mt = 0; mt < 2; mt++) {
                int rb = mw * 32 + mt * 16;
                af[mt][0] = __float_as_uint(Ps[kk + tig][rb + gid]);
                af[mt][1] = __float_as_uint(Ps[kk + tig][rb + gid + 8]);
                af[mt][2] = __float_as_uint(Ps[kk + tig + 4][rb + gid]);
                af[mt][3] = __float_as_uint(Ps[kk + tig + 4][rb + gid + 8]);
            }
            #pragma unroll
            for (int nt = 0; nt < 4; nt++) {
                int cb = nw * 32 + nt * 8;
                uint32_t bf[2];
                bf[0] = __float_as_uint(Hs[kk + tig][cb + gid]);
                bf[1] = __float_as_uint(Hs[kk + tig + 4][cb + gid]);
                mma8(acc[0][nt], af[0], bf);
                mma8(acc[1][nt], af[1], bf);
            }
        }
        __syncthreads();
    }
    float* pb = part + (size_t)kb * NN * FOUT;
    #pragma unroll
    for (int mt = 0; mt < 2; mt++) {
        int r0 = i0 + mw * 32 + mt * 16 + gid;
        #pragma unroll
        for (int nt = 0; nt < 4; nt++) {
            int c0 = nw * 32 + nt * 8 + tig * 2;
            float2 lo = {acc[mt][nt][0], acc[mt][nt][1]};
            float2 hi = {acc[mt][nt][2], acc[mt][nt][3]};
            *(float2*)(pb + (size_t)r0 * FOUT + c0) = lo;
            *(float2*)(pb + (size_t)(r0 + 8) * FOUT + c0) = hi;
        }
    }
}

// ---------------- combine partials + elu + log_softmax ----------------------
__global__ void combine_k(const float* __restrict__ part, float* __restrict__ out)
{
    int i = blockIdx.x, c = threadIdx.x;  // 64 threads
    float v = 0.f;
    #pragma unroll
    for (int k = 0; k < KSLICES; k++)
        v += part[(size_t)k * NN * FOUT + (size_t)i * FOUT + c];
    float e = v > 0.f ? v : expm1f(v);
    __shared__ float sh[4];
    float m = e;
    #pragma unroll
    for (int off = 16; off; off >>= 1)
        m = fmaxf(m, __shfl_xor_sync(0xffffffffu, m, off));
    if ((c & 31) == 0) sh[c >> 5] = m;
    __syncthreads();
    m = fmaxf(sh[0], sh[1]);
    float s = expf(e - m);
    #pragma unroll
    for (int off = 16; off; off >>= 1)
        s += __shfl_xor_sync(0xffffffffu, s, off);
    if ((c & 31) == 0) sh[2 + (c >> 5)] = s;
    __syncthreads();
    s = sh[2] + sh[3];
    out[(size_t)i * FOUT + c] = e - (m + logf(s));
}

// ---------------- launch -----------------------------------------------------
extern "C" void kernel_launch(void* const* d_in, const int* in_sizes, int n_in,
                              void* d_out, int out_size)
{
    const float* X    = (const float*)d_in[0];
    const int*   adj  = (const int*)  d_in[1];
    const float* W_h  = (const float*)d_in[2];
    const float* b_h  = (const float*)d_in[3];
    const float* a1_h = (const float*)d_in[4];
    const float* a2_h = (const float*)d_in[5];
    const float* ab_h = (const float*)d_in[6];
    const float* W_o  = (const float*)d_in[7];
    const float* b_o  = (const float*)d_in[8];
    const float* a1_o = (const float*)d_in[9];
    const float* a2_o = (const float*)d_in[10];
    const float* ab_o = (const float*)d_in[11];
    float* out = (float*)d_out;

    unsigned* bits; float *hcat, *x2, *h2, *s1, *t2, *c1, *s1o, *t2o, *c2, *p2;
    cudaGetSymbolAddress((void**)&bits, g_bits);
    cudaGetSymbolAddress((void**)&hcat, g_hcat);
    cudaGetSymbolAddress((void**)&x2,   g_x2);
    cudaGetSymbolAddress((void**)&h2,   g_h2);
    cudaGetSymbolAddress((void**)&s1,   g_s1);
    cudaGetSymbolAddress((void**)&t2,   g_t2);
    cudaGetSymbolAddress((void**)&c1,   g_c1);
    cudaGetSymbolAddress((void**)&s1o,  g_s1o);
    cudaGetSymbolAddress((void**)&t2o,  g_t2o);
    cudaGetSymbolAddress((void**)&c2,   g_c2);
    cudaGetSymbolAddress((void**)&p2,   g_p2);

    pack_k<<<NN, 128>>>(adj, bits);

    {   dim3 grid(NN / 64, NH);
        gemm1_k<<<grid, 128>>>(X, W_h, b_h, hcat); }

    {   dim3 grid(NN, NH);
        sdot_k<<<grid, FH>>>(hcat, FCAT, a1_h, a2_h, ab_h, s1, t2); }

    stats_k<NH><<<NN, 128>>>(bits, s1, t2, c1);

    {   dim3 grid(NN / 64, NH);
        agg1_k<<<grid, 128>>>(bits, s1, t2, c1, hcat, x2); }

    {   dim3 grid(1, NN / 64);
        gemm_bias_k<<<grid, 256>>>(x2, FCAT, W_o, FOUT, b_o, h2, FOUT, FCAT); }

    {   dim3 grid(NN, 1);
        sdot_k<<<grid, FOUT>>>(h2, FOUT, a1_o, a2_o, ab_o, s1o, t2o); }

    stats_k<1><<<NN, 128>>>(bits, s1o, t2o, c2);

    {   dim3 grid(NN / 64, KSLICES);
        agg2_k<<<grid, 128>>>(bits, s1o, t2o, c2, h2, p2); }

    combine_k<<<NN, 64>>>(p2, out);
}

// round 5
// speedup vs baseline: 2.2715x; 1.0154x over previous
#include <cuda_runtime.h>
#include <math.h>
#include <stdint.h>

#define NN    4096
#define FIN   512
#define FH    128
#define NH    4
#define FOUT  64
#define FCAT  512
#define KSLICES 8

// ---------------- scratch ----------------------------------------------------
__device__ unsigned g_bits[NN * NN / 32];
__device__ float g_hcat[NN * FCAT];
__device__ float g_x2  [NN * FCAT];
__device__ float g_h2  [NN * FOUT];
__device__ float g_s1  [NH * NN];
__device__ float g_t2  [NH * NN];
__device__ float g_s1o [NN];
__device__ float g_t2o [NN];
__device__ float g_T1  [NH];
__device__ float g_T2  [1];
__device__ float g_p2  [KSLICES * NN * FOUT];
__device__ float g_sp2 [KSLICES * NN];

// ---------------- helpers ----------------------------------------------------
__device__ __forceinline__ uint32_t f2tf32(float x) {
    uint32_t r;
    asm("cvt.rna.tf32.f32 %0, %1;" : "=r"(r) : "f"(x));
    return r;
}
__device__ __forceinline__ float tf32r(float x) { return __uint_as_float(f2tf32(x)); }
__device__ __forceinline__ void mma8(float* c, const uint32_t* a, const uint32_t* b) {
    asm volatile(
        "mma.sync.aligned.m16n8k8.row.col.f32.tf32.tf32.f32 "
        "{%0,%1,%2,%3},{%4,%5,%6,%7},{%8,%9},{%0,%1,%2,%3};"
        : "+f"(c[0]), "+f"(c[1]), "+f"(c[2]), "+f"(c[3])
        : "r"(a[0]), "r"(a[1]), "r"(a[2]), "r"(a[3]), "r"(b[0]), "r"(b[1]));
}

// ---------------- pack adjacency to bits ------------------------------------
__global__ __launch_bounds__(128) void pack_k(const int* __restrict__ adj,
                                              unsigned* __restrict__ bits)
{
    int i = blockIdx.x;
    int t = threadIdx.x, lane = t & 31, w = t >> 5;
    for (int wd = w; wd < NN / 32; wd += 4) {
        int a = adj[(size_t)i * NN + wd * 32 + lane];
        unsigned m = __ballot_sync(0xffffffffu, a > 0);
        if (lane == 0) bits[i * (NN / 32) + wd] = m;
    }
}

// ---------------- stage1 feature GEMM (tf32 mma) -----------------------------
__global__ __launch_bounds__(128) void gemm1_k(
    const float* __restrict__ A, const float* __restrict__ W,
    const float* __restrict__ bias, float* __restrict__ C)
{
    __shared__ float As[16][72];
    __shared__ float Bs[16][136];
    const int head = blockIdx.y;
    const int rowBase = blockIdx.x * 64;
    const int t = threadIdx.x;
    const int lane = t & 31, wid = t >> 5;
    const int gid = lane >> 2, tig = lane & 3;
    const int mw = wid >> 1, nw = wid & 1;
    const float* Wh = W + (size_t)head * FIN * FH;

    float acc[2][8][4] = {};

    for (int k0 = 0; k0 < FIN; k0 += 16) {
        {
            int r = t >> 1, kc = (t & 1) << 3;
            float4 a0 = *(const float4*)(A + (size_t)(rowBase + r) * FIN + k0 + kc);
            float4 a1 = *(const float4*)(A + (size_t)(rowBase + r) * FIN + k0 + kc + 4);
            As[kc + 0][r] = tf32r(a0.x); As[kc + 1][r] = tf32r(a0.y);
            As[kc + 2][r] = tf32r(a0.z); As[kc + 3][r] = tf32r(a0.w);
            As[kc + 4][r] = tf32r(a1.x); As[kc + 5][r] = tf32r(a1.y);
            As[kc + 6][r] = tf32r(a1.z); As[kc + 7][r] = tf32r(a1.w);
        }
        #pragma unroll
        for (int v = 0; v < 4; v++) {
            int idx = t + v * 128;
            int kr = idx >> 5, cc = (idx & 31) << 2;
            float4 b = *(const float4*)(Wh + (size_t)(k0 + kr) * FH + cc);
            float4 o = {tf32r(b.x), tf32r(b.y), tf32r(b.z), tf32r(b.w)};
            *(float4*)&Bs[kr][cc] = o;
        }
        __syncthreads();
        #pragma unroll
        for (int kc = 0; kc < 2; kc++) {
            int kk = kc * 8;
            uint32_t af[2][4];
            #pragma unroll
            for (int mt = 0; mt < 2; mt++) {
                int rb = mw * 32 + mt * 16;
                af[mt][0] = __float_as_uint(As[kk + tig][rb + gid]);
                af[mt][1] = __float_as_uint(As[kk + tig][rb + gid + 8]);
                af[mt][2] = __float_as_uint(As[kk + tig + 4][rb + gid]);
                af[mt][3] = __float_as_uint(As[kk + tig + 4][rb + gid + 8]);
            }
            #pragma unroll
            for (int nt = 0; nt < 8; nt++) {
                int cb = nw * 64 + nt * 8;
                uint32_t bf[2];
                bf[0] = __float_as_uint(Bs[kk + tig][cb + gid]);
                bf[1] = __float_as_uint(Bs[kk + tig + 4][cb + gid]);
                mma8(acc[0][nt], af[0], bf);
                mma8(acc[1][nt], af[1], bf);
            }
        }
        __syncthreads();
    }
    #pragma unroll
    for (int mt = 0; mt < 2; mt++) {
        int r0 = rowBase + mw * 32 + mt * 16 + gid;
        #pragma unroll
        for (int nt = 0; nt < 8; nt++) {
            int c0 = nw * 64 + nt * 8 + tig * 2;
            float b0 = bias[head * FH + c0], b1 = bias[head * FH + c0 + 1];
            float2 lo = {acc[mt][nt][0] + b0, acc[mt][nt][1] + b1};
            float2 hi = {acc[mt][nt][2] + b0, acc[mt][nt][3] + b1};
            *(float2*)(C + (size_t)r0 * FCAT + head * FH + c0) = lo;
            *(float2*)(C + (size_t)(r0 + 8) * FCAT + head * FH + c0) = hi;
        }
    }
}

// ---------------- attention logits ------------------------------------------
__global__ void sdot_k(const float* __restrict__ Hmat, int ldh,
                       const float* __restrict__ a1, const float* __restrict__ a2,
                       const float* __restrict__ ab,
                       float* __restrict__ s1, float* __restrict__ t2)
{
    int i = blockIdx.x, h = blockIdx.y;
    int F = blockDim.x, f = threadIdx.x;
    float v  = Hmat[(size_t)i * ldh + h * F + f];
    float p1 = v * a1[h * F + f];
    float p2 = v * a2[h * F + f];
    #pragma unroll
    for (int off = 16; off; off >>= 1) {
        p1 += __shfl_xor_sync(0xffffffffu, p1, off);
        p2 += __shfl_xor_sync(0xffffffffu, p2, off);
    }
    __shared__ float r1[4], r2[4];
    int w = f >> 5;
    if ((f & 31) == 0) { r1[w] = p1; r2[w] = p2; }
    __syncthreads();
    if (f == 0) {
        float a = 0.f, b = 0.f;
        int nw = F >> 5;
        for (int k = 0; k < nw; k++) { a += r1[k]; b += r2[k]; }
        s1[h * NN + i] = a;
        t2[h * NN + i] = b + ab[h];
    }
}

// ---------------- global max of t2 per head ----------------------------------
__global__ __launch_bounds__(256) void tmax_k(const float* __restrict__ t2,
                                              float* __restrict__ T, int n)
{
    int h = blockIdx.x;
    const float* p = t2 + (size_t)h * n;
    float m = -3.0e38f;
    for (int j = threadIdx.x; j < n; j += 256) m = fmaxf(m, p[j]);
    #pragma unroll
    for (int off = 16; off; off >>= 1)
        m = fmaxf(m, __shfl_xor_sync(0xffffffffu, m, off));
    __shared__ float sh[8];
    if ((threadIdx.x & 31) == 0) sh[threadIdx.x >> 5] = m;
    __syncthreads();
    if (threadIdx.x == 0) {
        float r = sh[0];
        for (int k = 1; k < 8; k++) r = fmaxf(r, sh[k]);
        T[h] = r;
    }
}

// ---------------- stage1 aggregation: elu((P@h)/rowsum), on-the-fly P -------
// BM=128, BN=128, BK=32, 256 threads, warps 4Mx2N (warp tile 32x64)
__global__ __launch_bounds__(256) void agg1_k(
    const unsigned* __restrict__ bits,
    const float* __restrict__ s1a, const float* __restrict__ t2a,
    const float* __restrict__ Tg,
    const float* __restrict__ Hmat, float* __restrict__ outm)
{
    __shared__ float Ps[32][136];
    __shared__ float Hs[32][136];
    __shared__ float s1s[128], cs[128], invs[128];
    __shared__ float spart[16][128];

    const int head = blockIdx.y;
    const int i0 = blockIdx.x * 128;
    const int t = threadIdx.x;
    const int lane = t & 31, wid = t >> 5;
    const int gid = lane >> 2, tig = lane & 3;
    const int mw = wid >> 1, nw = wid & 1;
    if (t < 128) {
        float s = s1a[head * NN + i0 + t];
        s1s[t] = s;
        float z = s + Tg[head];
        cs[t] = fmaxf(z, 0.2f * z);
    }
    const float* t2h = t2a + head * NN;
    const int pk  = (lane & 3) + ((wid & 3) << 2);   // 0..15
    const int pr0 = (lane >> 2) + ((wid >> 2) << 3); // 0..15
    __syncthreads();

    float acc[2][8][4] = {};
    float psum[8] = {};

    for (int j0 = 0; j0 < NN; j0 += 32) {
        // ---- P tile 128x32: one bits word covers both columns pk, pk+16
        const float tv0 = t2h[j0 + pk];
        const float tv1 = t2h[j0 + pk + 16];
        const int wcol = j0 >> 5;
        unsigned wreg[8];
        #pragma unroll
        for (int v = 0; v < 8; v++)
            wreg[v] = bits[(size_t)(i0 + pr0 + 16 * v) * (NN / 32) + wcol];
        #pragma unroll
        for (int v = 0; v < 8; v++) {
            int r = pr0 + 16 * v;
            float z0 = s1s[r] + tv0;
            float z1 = s1s[r] + tv1;
            float l0 = fmaxf(z0, 0.2f * z0);
            float l1 = fmaxf(z1, 0.2f * z1);
            float p0 = ((wreg[v] >> pk) & 1u)        ? tf32r(__expf(l0 - cs[r])) : 0.f;
            float p1 = ((wreg[v] >> (pk + 16)) & 1u) ? tf32r(__expf(l1 - cs[r])) : 0.f;
            psum[v] += p0 + p1;
            Ps[pk][r] = p0;
            Ps[pk + 16][r] = p1;
        }
        // ---- H tile 32x128 (FIX: 4 iterations => all 32 rows loaded)
        #pragma unroll
        for (int v = 0; v < 4; v++) {
            int idx = t + v * 256;
            int kr = idx >> 5, cc = (idx & 31) << 2;
            float4 b = *(const float4*)(Hmat + (size_t)(j0 + kr) * FCAT + head * FH + cc);
            float4 o = {tf32r(b.x), tf32r(b.y), tf32r(b.z), tf32r(b.w)};
            *(float4*)&Hs[kr][cc] = o;
        }
        __syncthreads();
        #pragma unroll
        for (int kc = 0; kc < 4; kc++) {
            int kk = kc * 8;
            uint32_t af[2][4];
            #pragma unroll
            for (int mt = 0; mt < 2; mt++) {
                int rb = mw * 32 + mt * 16;
                af[mt][0] = __float_as_uint(Ps[kk + tig][rb + gid]);
                af[mt][1] = __float_as_uint(Ps[kk + tig][rb + gid + 8]);
                af[mt][2] = __float_as_uint(Ps[kk + tig + 4][rb + gid]);
                af[mt][3] = __float_as_uint(Ps[kk + tig + 4][rb + gid + 8]);
            }
            #pragma unroll
            for (int nt = 0; nt < 8; nt++) {
                int cb = nw * 64 + nt * 8;
                uint32_t bf[2];
                bf[0] = __float_as_uint(Hs[kk + tig][cb + gid]);
                bf[1] = __float_as_uint(Hs[kk + tig + 4][cb + gid]);
                mma8(acc[0][nt], af[0], bf);
                mma8(acc[1][nt], af[1], bf);
            }
        }
        __syncthreads();
    }
    // ---- row-sum reduce -> invs
    #pragma unroll
    for (int v = 0; v < 8; v++) spart[pk][pr0 + 16 * v] = psum[v];
    __syncthreads();
    if (t < 128) {
        float s = 0.f;
        #pragma unroll
        for (int q = 0; q < 16; q++) s += spart[q][t];
        invs[t] = 1.f / s;
    }
    __syncthreads();
    // ---- epilogue: normalize, elu, store
    #pragma unroll
    for (int mt = 0; mt < 2; mt++) {
        int rl = mw * 32 + mt * 16 + gid;
        float invLo = invs[rl], invHi = invs[rl + 8];
        int r0 = i0 + rl;
        #pragma unroll
        for (int nt = 0; nt < 8; nt++) {
            int c0 = head * FH + nw * 64 + nt * 8 + tig * 2;
            float v; float2 lo, hi;
            v = acc[mt][nt][0] * invLo; lo.x = v > 0.f ? v : expm1f(v);
            v = acc[mt][nt][1] * invLo; lo.y = v > 0.f ? v : expm1f(v);
            v = acc[mt][nt][2] * invHi; hi.x = v > 0.f ? v : expm1f(v);
            v = acc[mt][nt][3] * invHi; hi.y = v > 0.f ? v : expm1f(v);
            *(float2*)(outm + (size_t)r0 * FCAT + c0) = lo;
            *(float2*)(outm + (size_t)(r0 + 8) * FCAT + c0) = hi;
        }
    }
}

// ---------------- stage2 feature GEMM (small, SIMT) --------------------------
__global__ __launch_bounds__(256) void gemm_bias_k(
    const float* __restrict__ A, int lda,
    const float* __restrict__ B, int ldb,
    const float* __restrict__ bias,
    float* __restrict__ C, int ldc, int K)
{
    const int BM = 64, BN = 64, BK = 16;
    __shared__ float As[BK][BM];
    __shared__ float Bs[BK][BN];
    const int rowBase = blockIdx.y * BM;
    const int tid = threadIdx.x;
    const int tx = tid & 15, ty = tid >> 4;
    float acc[4][4] = {};
    for (int k0 = 0; k0 < K; k0 += BK) {
        {
            int r = tid >> 2, kc = (tid & 3) << 2;
            float4 a = *(const float4*)(A + (size_t)(rowBase + r) * lda + k0 + kc);
            As[kc + 0][r] = a.x; As[kc + 1][r] = a.y;
            As[kc + 2][r] = a.z; As[kc + 3][r] = a.w;
            int kr = tid >> 4, c = (tid & 15) << 2;
            *(float4*)&Bs[kr][c] = *(const float4*)(B + (size_t)(k0 + kr) * ldb + c);
        }
        __syncthreads();
        #pragma unroll
        for (int k = 0; k < BK; k++) {
            float4 ra = *(const float4*)&As[k][ty << 2];
            float4 rb = *(const float4*)&Bs[k][tx << 2];
            float av[4] = {ra.x, ra.y, ra.z, ra.w};
            float bv[4] = {rb.x, rb.y, rb.z, rb.w};
            #pragma unroll
            for (int i = 0; i < 4; i++)
                #pragma unroll
                for (int j = 0; j < 4; j++)
                    acc[i][j] = fmaf(av[i], bv[j], acc[i][j]);
        }
        __syncthreads();
    }
    #pragma unroll
    for (int i = 0; i < 4; i++) {
        int r = rowBase + (ty << 2) + i;
        float4 o;
        o.x = acc[i][0] + bias[(tx << 2) + 0];
        o.y = acc[i][1] + bias[(tx << 2) + 1];
        o.z = acc[i][2] + bias[(tx << 2) + 2];
        o.w = acc[i][3] + bias[(tx << 2) + 3];
        *(float4*)(C + (size_t)r * ldc + (tx << 2)) = o;
    }
}

// ---------------- stage2 aggregation split-K (tf32 mma) ---------------------
// BM=128, BN=64, BK=32, 256 threads, warps 4Mx2N (warp tile 32x32)
__global__ __launch_bounds__(256) void agg2_k(
    const unsigned* __restrict__ bits,
    const float* __restrict__ s1a, const float* __restrict__ t2a,
    const float* __restrict__ Tg,
    const float* __restrict__ Hmat,
    float* __restrict__ part, float* __restrict__ psums)
{
    __shared__ float Ps[32][136];
    __shared__ float Hs[32][72];
    __shared__ float s1s[128], cs[128];
    __shared__ float spart[16][128];

    const int i0 = blockIdx.x * 128;
    const int kb = blockIdx.y;
    const int t = threadIdx.x;
    const int lane = t & 31, wid = t >> 5;
    const int gid = lane >> 2, tig = lane & 3;
    const int mw = wid >> 1, nw = wid & 1;
    if (t < 128) {
        float s = s1a[i0 + t];
        s1s[t] = s;
        float z = s + Tg[0];
        cs[t] = fmaxf(z, 0.2f * z);
    }
    const int pk  = (lane & 3) + ((wid & 3) << 2);
    const int pr0 = (lane >> 2) + ((wid >> 2) << 3);
    __syncthreads();

    float acc[2][4][4] = {};
    float psum[8] = {};
    const int js = kb * (NN / KSLICES);
    const int je = js + (NN / KSLICES);

    for (int j0 = js; j0 < je; j0 += 32) {
        const float tv0 = t2a[j0 + pk];
        const float tv1 = t2a[j0 + pk + 16];
        const int wcol = j0 >> 5;
        unsigned wreg[8];
        #pragma unroll
        for (int v = 0; v < 8; v++)
            wreg[v] = bits[(size_t)(i0 + pr0 + 16 * v) * (NN / 32) + wcol];
        #pragma unroll
        for (int v = 0; v < 8; v++) {
            int r = pr0 + 16 * v;
            float z0 = s1s[r] + tv0;
            float z1 = s1s[r] + tv1;
            float l0 = fmaxf(z0, 0.2f * z0);
            float l1 = fmaxf(z1, 0.2f * z1);
            float p0 = ((wreg[v] >> pk) & 1u)        ? tf32r(__expf(l0 - cs[r])) : 0.f;
            float p1 = ((wreg[v] >> (pk + 16)) & 1u) ? tf32r(__expf(l1 - cs[r])) : 0.f;
            psum[v] += p0 + p1;
            Ps[pk][r] = p0;
            Ps[pk + 16][r] = p1;
        }
        #pragma unroll
        for (int v = 0; v < 2; v++) {
            int idx = t + v * 256;
            int kr = idx >> 4, cc = (idx & 15) << 2;
            float4 b = *(const float4*)(Hmat + (size_t)(j0 + kr) * FOUT + cc);
            float4 o = {tf32r(b.x), tf32r(b.y), tf32r(b.z), tf32r(b.w)};
            *(float4*)&Hs[kr][cc] = o;
        }
        __syncthreads();
        #pragma unroll
        for (int kc = 0; kc < 4; kc++) {
            int kk = kc * 8;
            uint32_t af[2][4];
            #pragma unroll
            for (int mt = 0; mt < 2; mt++) {
                int rb = mw * 32 + mt * 16;
                af[mt][0] = __float_as_uint(Ps[kk + tig][rb + gid]);
                af[mt][1] = __float_as_uint(Ps[kk + tig][rb + gid + 8]);
                af[mt][2] = __float_as_uint(Ps[kk + tig + 4][rb + gid]);
                af[mt][3] = __float_as_uint(Ps[kk + tig + 4][rb + gid + 8]);
            }
            #pragma unroll
            for (int nt = 0; nt < 4; nt++) {
                int cb = nw * 32 + nt * 8;
                uint32_t bf[2];
                bf[0] = __float_as_uint(Hs[kk + tig][cb + gid]);
                bf[1] = __float_as_uint(Hs[kk + tig + 4][cb + gid]);
                mma8(acc[0][nt], af[0], bf);
                mma8(acc[1][nt], af[1], bf);
            }
        }
        __syncthreads();
    }
    #pragma unroll
    for (int v = 0; v < 8; v++) spart[pk][pr0 + 16 * v] = psum[v];
    __syncthreads();
    if (t < 128) {
        float s = 0.f;
        #pragma unroll
        for (int q = 0; q < 16; q++) s += spart[q][t];
        psums[(size_t)kb * NN + i0 + t] = s;
    }
    float* pb = part + (size_t)kb * NN * FOUT;
    #pragma unroll
    for (int mt = 0; mt < 2; mt++) {
        int r0 = i0 + mw * 32 + mt * 16 + gid;
        #pragma unroll
        for (int nt = 0; nt < 4; nt++) {
            int c0 = nw * 32 + nt * 8 + tig * 2;
            float2 lo = {acc[mt][nt][0], acc[mt][nt][1]};
            float2 hi = {acc[mt][nt][2], acc[mt][nt][3]};
            *(float2*)(pb + (size_t)r0 * FOUT + c0) = lo;
            *(float2*)(pb + (size_t)(r0 + 8) * FOUT + c0) = hi;
        }
    }
}

// ---------------- combine partials + normalize + elu + log_softmax ----------
__global__ void combine_k(const float* __restrict__ part,
                          const float* __restrict__ psums,
                          float* __restrict__ out)
{
    int i = blockIdx.x, c = threadIdx.x;  // 64 threads
    float v = 0.f, s = 0.f;
    #pragma unroll
    for (int k = 0; k < KSLICES; k++) {
        v += part[(size_t)k * NN * FOUT + (size_t)i * FOUT + c];
        s += psums[(size_t)k * NN + i];
    }
    v /= s;
    float e = v > 0.f ? v : expm1f(v);
    __shared__ float sh[4];
    float m = e;
    #pragma unroll
    for (int off = 16; off; off >>= 1)
        m = fmaxf(m, __shfl_xor_sync(0xffffffffu, m, off));
    if ((c & 31) == 0) sh[c >> 5] = m;
    __syncthreads();
    m = fmaxf(sh[0], sh[1]);
    float se = expf(e - m);
    #pragma unroll
    for (int off = 16; off; off >>= 1)
        se += __shfl_xor_sync(0xffffffffu, se, off);
    if ((c & 31) == 0) sh[2 + (c >> 5)] = se;
    __syncthreads();
    se = sh[2] + sh[3];
    out[(size_t)i * FOUT + c] = e - (m + logf(se));
}

// ---------------- launch -----------------------------------------------------
extern "C" void kernel_launch(void* const* d_in, const int* in_sizes, int n_in,
                              void* d_out, int out_size)
{
    const float* X    = (const float*)d_in[0];
    const int*   adj  = (const int*)  d_in[1];
    const float* W_h  = (const float*)d_in[2];
    const float* b_h  = (const float*)d_in[3];
    const float* a1_h = (const float*)d_in[4];
    const float* a2_h = (const float*)d_in[5];
    const float* ab_h = (const float*)d_in[6];
    const float* W_o  = (const float*)d_in[7];
    const float* b_o  = (const float*)d_in[8];
    const float* a1_o = (const float*)d_in[9];
    const float* a2_o = (const float*)d_in[10];
    const float* ab_o = (const float*)d_in[11];
    float* out = (float*)d_out;

    unsigned* bits; float *hcat, *x2, *h2, *s1, *t2, *s1o, *t2o, *T1, *T2, *p2, *sp2;
    cudaGetSymbolAddress((void**)&bits, g_bits);
    cudaGetSymbolAddress((void**)&hcat, g_hcat);
    cudaGetSymbolAddress((void**)&x2,   g_x2);
    cudaGetSymbolAddress((void**)&h2,   g_h2);
    cudaGetSymbolAddress((void**)&s1,   g_s1);
    cudaGetSymbolAddress((void**)&t2,   g_t2);
    cudaGetSymbolAddress((void**)&s1o,  g_s1o);
    cudaGetSymbolAddress((void**)&t2o,  g_t2o);
    cudaGetSymbolAddress((void**)&T1,   g_T1);
    cudaGetSymbolAddress((void**)&T2,   g_T2);
    cudaGetSymbolAddress((void**)&p2,   g_p2);
    cudaGetSymbolAddress((void**)&sp2,  g_sp2);

    pack_k<<<NN, 128>>>(adj, bits);

    {   dim3 grid(NN / 64, NH);
        gemm1_k<<<grid, 128>>>(X, W_h, b_h, hcat); }

    {   dim3 grid(NN, NH);
        sdot_k<<<grid, FH>>>(hcat, FCAT, a1_h, a2_h, ab_h, s1, t2); }

    tmax_k<<<NH, 256>>>(t2, T1, NN);

    {   dim3 grid(NN / 128, NH);
        agg1_k<<<grid, 256>>>(bits, s1, t2, T1, hcat, x2); }

    {   dim3 grid(1, NN / 64);
        gemm_bias_k<<<grid, 256>>>(x2, FCAT, W_o, FOUT, b_o, h2, FOUT, FCAT); }

    {   dim3 grid(NN, 1);
        sdot_k<<<grid, FOUT>>>(h2, FOUT, a1_o, a2_o, ab_o, s1o, t2o); }

    tmax_k<<<1, 256>>>(t2o, T2, NN);

    {   dim3 grid(NN / 128, KSLICES);
        agg2_k<<<grid, 256>>>(bits, s1o, t2o, T2, h2, p2, sp2); }

    combine_k<<<NN, 64>>>(p2, sp2, out);
}